// round 9
// baseline (speedup 1.0000x reference)
#include <cuda_runtime.h>
#include <cuda_bf16.h>
#include <cstdint>
#include <math.h>

// ---------------- device scratch ----------------
__device__ float  g_xt [6291456];              // x NHWC [32,256,256,3] fp32
__device__ __nv_bfloat16 g_h1b[33554432];      // [32,128,128,64] NHWC bf16
__device__ __nv_bfloat16 g_h2b[16777216];      // [32,64,64,128]  NHWC bf16
__device__ float  g_z  [8388608];              // [32,64,64,64] fp32 (VQ/loss path)
__device__ __nv_bfloat16 g_qb [8388608];       // q bf16 (decoder input)
__device__ __nv_bfloat16 g_d1b[67108864];      // [32,128,128,128] bf16
__device__ __nv_bfloat16 g_d2b[134217728];     // [32,256,256,64]  bf16
__device__ float  g_col[25165824];             // L1 im2col (fp32)
__device__ float  g_wb1[64*48];
__device__ __nv_bfloat16 g_wb2b[131072];
__device__ __nv_bfloat16 g_wb3b[73728];
__device__ __nv_bfloat16 g_wbd[32768];
__device__ float  g_enorm[512];
__device__ double g_loss;

__device__ __forceinline__ uint32_t smem_u32(const void* p) {
    uint32_t a;
    asm("{ .reg .u64 t; cvta.to.shared.u64 t, %1; cvt.u32.u64 %0, t; }" : "=r"(a) : "l"(p));
    return a;
}
__device__ __forceinline__ uint32_t swz(uint32_t off) { return off ^ ((off >> 3) & 0x70); }
__device__ __forceinline__ void cpa16(uint32_t dst, const void* src, bool ok) {
    asm volatile("cp.async.cg.shared.global [%0], [%1], 16, %2;"
                 :: "r"(dst), "l"(src), "r"(ok ? 16 : 0) : "memory");
}
__device__ __forceinline__ void cpa_commit() {
    asm volatile("cp.async.commit_group;" ::: "memory");
}
template<int N>
__device__ __forceinline__ void cpa_wait() {
    asm volatile("cp.async.wait_group %0;" :: "n"(N) : "memory");
}

// ---------------- small kernels ----------------
__global__ void nchw_to_nhwc_x(const float* __restrict__ in, float* __restrict__ out) {
    int idx = blockIdx.x * 256 + threadIdx.x;            // 32*65536
    int n = idx >> 16, yx = idx & 65535;
    const float* ib = in + (long)n * 196608 + yx;
    float* ob = out + (long)idx * 3;
    ob[0] = ib[0]; ob[1] = ib[65536]; ob[2] = ib[131072];
}

__global__ void pack_conv_w(const float* __restrict__ w, float* __restrict__ bw,
                            int Cout, int Cin, int KH, int KW) {
    int idx = blockIdx.x * 256 + threadIdx.x;
    int K = Cin * KH * KW;
    if (idx >= Cout * K) return;
    int co = idx / K, rem = idx % K;
    int ci = rem / (KH * KW), r2 = rem % (KH * KW);
    bw[(long)co * K + r2 * Cin + ci] = w[idx];
}

__global__ void pack_conv_w_bf16(const float* __restrict__ w, __nv_bfloat16* __restrict__ bw,
                                 int Cout, int Cin, int KH, int KW) {
    int idx = blockIdx.x * 256 + threadIdx.x;
    int K = Cin * KH * KW;
    if (idx >= Cout * K) return;
    int co = idx / K, rem = idx % K;
    int ci = rem / (KH * KW), r2 = rem % (KH * KW);
    bw[(long)co * K + r2 * Cin + ci] = __float2bfloat16(w[idx]);
}

__global__ void pack_deconv_w_bf16(const float* __restrict__ w, __nv_bfloat16* __restrict__ bw,
                                   int Cin, int Cout, int py, int px) {
    int idx = blockIdx.x * 256 + threadIdx.x;
    if (idx >= Cout * Cin * 4) return;
    int co = idx / (Cin * 4), rem = idx % (Cin * 4);
    int ci = rem / 4, tt = rem % 4;
    int ky = (1 - py) + 2 * (tt >> 1), kx = (1 - px) + 2 * (tt & 1);
    bw[(long)co * (4 * Cin) + tt * Cin + ci] =
        __float2bfloat16(w[(((long)ci * Cout + co) * 4 + ky) * 4 + kx]);
}

__global__ void compute_enorm(const float* __restrict__ emb, float* __restrict__ en) {
    int j = blockIdx.x * 256 + threadIdx.x;
    if (j >= 512) return;
    float s = 0.f;
    const float* e = emb + (long)j * 64;
#pragma unroll 8
    for (int d = 0; d < 64; ++d) { float v = e[d]; s = fmaf(v, v, s); }
    en[j] = s;
}

__global__ void zero_loss() { g_loss = 0.0; }
__global__ void finalize_loss(float* out, long pos) {
    out[pos] = (float)(1.25 * g_loss / 8388608.0);
}

// ---------------- explicit im2col (L1 only, CIN=3, fp32) ----------------
template<int CIN, int KH, int KW, int ST, int PAD, int IH, int IW, int OW, int KT, int MB>
__global__ void __launch_bounds__(256)
im2col_conv(const float* __restrict__ in, float* __restrict__ col) {
    constexpr int K = KH * KW * CIN;
    int mi = threadIdx.x / KT, kt = threadIdx.x % KT;
    int m = blockIdx.x * MB + mi;
    int n = m / (OW * OW);
    int r = m % (OW * OW);
    int oy = r / OW, ox = r % OW;
    const float* inb = in + (long)n * IH * IW * CIN;
    float* colr = col + (long)m * K;
    for (int k = kt; k < K; k += KT) {
        int ci = k % CIN, t = k / CIN;
        int kx = t % KW, ky = t / KW;
        int iy = oy * ST - PAD + ky, ix = ox * ST - PAD + kx;
        float v = 0.f;
        if (iy >= 0 && iy < IH && ix >= 0 && ix < IW)
            v = inb[((long)iy * IW + ix) * CIN + ci];
        colr[k] = v;
    }
}

// ---------------- A loaders (address-producing, bf16) ----------------
struct DenseLoader {
    const float* A; int ldk;
    const float* p;
    __device__ void init(int m) { p = A + (long)m * ldk; }
    __device__ void load8(int k, float4& a0, float4& a1) const {
        a0 = *(const float4*)(p + k);
        a1 = *(const float4*)(p + k + 4);
    }
};

// k must stay within one (ky,kx) tap for the thread's segment (guaranteed:
// segments are 32/64-k aligned and CIN in {64,128}).
template<int CIN, int KH, int KW, int ST, int PAD, int IH, int IW, int OW>
struct ConvLoaderB {
    const __nv_bfloat16* in;
    const __nv_bfloat16* base; int oy, ox;
    __device__ void init(int m) {
        int n = m / (OW * OW);
        int r = m % (OW * OW);
        oy = r / OW; ox = r % OW;
        base = in + (long)n * IH * IW * CIN;
    }
    __device__ const __nv_bfloat16* addr(int k, bool& ok) const {
        int ci = k % CIN, t = k / CIN;
        int ky = t / KW, kx = t % KW;
        int iy = oy * ST - PAD + ky, ix = ox * ST - PAD + kx;
        ok = (iy >= 0 && iy < IH && ix >= 0 && ix < IW);
        return ok ? base + ((long)iy * IW + ix) * CIN + ci : base;
    }
};

template<int CIN, int IH, int IW>
struct DeconvLoaderB {
    const __nv_bfloat16* in; int py, px;
    const __nv_bfloat16* base; int u, v;
    __device__ void init(int m) {
        int n = m / (IH * IW);
        int r = m % (IH * IW);
        u = r / IW; v = r % IW;
        base = in + (long)n * IH * IW * CIN;
    }
    __device__ const __nv_bfloat16* addr(int k, bool& ok) const {
        int ci = k % CIN, t = k / CIN;
        int iy = u + py - (t >> 1), ix = v + px - (t & 1);
        ok = (iy >= 0 && iy < IH && ix >= 0 && ix < IW);
        return ok ? base + ((long)iy * IW + ix) * CIN + ci : base;
    }
};

// ---------------- epilogue descriptor ----------------
struct Epi {
    float* out; const float* bias;
    int mode, act, ldc;          // mode 0: row-major; 1: deconv NHWC scatter
    int MPN, OV, W2, C, py, px;
    long nstride;
};

__device__ __forceinline__ long epi_base(const Epi& ep, int m) {
    if (ep.mode == 0) return (long)m * ep.ldc;
    int nn = m / ep.MPN, r = m % ep.MPN;
    int u = r / ep.OV, v = r % ep.OV;
    return (long)nn * ep.nstride +
           ((long)(2*u + ep.py) * ep.W2 + (2*v + ep.px)) * ep.C;
}

// ---------------- fp32 SGEMM (L1 only), bf16 output ----------------
template<class LD>
__global__ void __launch_bounds__(256)
sgemm_t(LD ld, const float* __restrict__ Bm, int K, Epi ep, __nv_bfloat16* outb) {
    __shared__ float As[16][132];
    __shared__ float Bs[16][68];
    const int tid = threadIdx.x;
    const int m0 = blockIdx.y * 128, n0 = blockIdx.x * 64;
    const int tx = tid & 15, ty = tid >> 4;
    const int ra = tid >> 1, ca = (tid & 1) * 8;
    const int rb = tid >> 2, cb = (tid & 3) * 4;
    float acc[8][4] = {};
    ld.init(m0 + ra);
    const float* Bptr = Bm + (long)(n0 + rb) * K + cb;

    for (int k0 = 0; k0 < K; k0 += 16) {
        float4 a0, a1;
        ld.load8(k0 + ca, a0, a1);
        float4 b0 = *(const float4*)(Bptr + k0);
        As[ca+0][ra]=a0.x; As[ca+1][ra]=a0.y; As[ca+2][ra]=a0.z; As[ca+3][ra]=a0.w;
        As[ca+4][ra]=a1.x; As[ca+5][ra]=a1.y; As[ca+6][ra]=a1.z; As[ca+7][ra]=a1.w;
        Bs[cb+0][rb]=b0.x; Bs[cb+1][rb]=b0.y; Bs[cb+2][rb]=b0.z; Bs[cb+3][rb]=b0.w;
        __syncthreads();
#pragma unroll
        for (int kk = 0; kk < 16; ++kk) {
            float4 aA = *(const float4*)&As[kk][ty*8];
            float4 aB = *(const float4*)&As[kk][ty*8+4];
            float4 bb = *(const float4*)&Bs[kk][tx*4];
            float av[8] = {aA.x,aA.y,aA.z,aA.w,aB.x,aB.y,aB.z,aB.w};
            float bv[4] = {bb.x,bb.y,bb.z,bb.w};
#pragma unroll
            for (int i = 0; i < 8; ++i)
#pragma unroll
                for (int j = 0; j < 4; ++j)
                    acc[i][j] = fmaf(av[i], bv[j], acc[i][j]);
        }
        __syncthreads();
    }

    const int n_base = n0 + tx * 4;
    float bvals[4];
#pragma unroll
    for (int j = 0; j < 4; ++j) bvals[j] = ep.bias ? ep.bias[n_base + j] : 0.f;
#pragma unroll
    for (int i = 0; i < 8; ++i) {
        int m = m0 + ty * 8 + i;
        long base = (long)m * ep.ldc + n_base;
        float v0 = fmaxf(acc[i][0] + bvals[0], 0.f);
        float v1 = fmaxf(acc[i][1] + bvals[1], 0.f);
        float v2 = fmaxf(acc[i][2] + bvals[2], 0.f);
        float v3 = fmaxf(acc[i][3] + bvals[3], 0.f);
        __nv_bfloat162 p0 = __floats2bfloat162_rn(v0, v1);
        __nv_bfloat162 p1 = __floats2bfloat162_rn(v2, v3);
        uint2 u; u.x = *(uint32_t*)&p0; u.y = *(uint32_t*)&p1;
        *(uint2*)(outb + base) = u;
    }
}

// ---------------- HMMA bf16 GEMM v2: 256xTN tile, 64x32 warp tiles, cp.async ----------------
// warps: 4(m) x TN/32(n); threads = 4*TN. K multiple of 64, 2-stage pipeline.
template<class LD, int TN, bool OBF>
__global__ void __launch_bounds__(4*TN)
hgemm2(LD ld, const __nv_bfloat16* __restrict__ Bw, int K, Epi ep) {
    constexpr int T    = 4 * TN;        // 256 or 512
    constexpr int TPR  = TN / 64;       // threads per A row: 1 or 2
    constexpr int KP   = 64 / TPR;      // k-values per thread segment
    constexpr int NCA  = KP / 8;        // 16B cp.asyncs per thread (A)
    constexpr uint32_t ABUF = 256 * 128;
    constexpr uint32_t BBUF = (uint32_t)TN * 128;
    extern __shared__ char dynsm[];
    const uint32_t sA0 = smem_u32(dynsm);
    const uint32_t sB0 = sA0 + 2 * ABUF;

    const int tid = threadIdx.x;
    const int wid = tid >> 5, lane = tid & 31;
    const int m0 = blockIdx.y * 256;
    const int wm = (wid & 3) * 64;
    const int wn = (wid >> 2) * 32;

    const int row  = tid / TPR;
    const int part = tid % TPR;
    ld.init(m0 + row);

    float acc[4][4][4];
#pragma unroll
    for (int i = 0; i < 4; ++i)
#pragma unroll
        for (int j = 0; j < 4; ++j)
#pragma unroll
            for (int c = 0; c < 4; ++c) acc[i][j][c] = 0.f;

    // stage fill via cp.async
    auto fill = [&](int k0, int s) {
        bool ok;
        const __nv_bfloat16* p = ld.addr(k0 + part * KP, ok);
        uint32_t aDst = sA0 + s * ABUF;
#pragma unroll
        for (int j = 0; j < NCA; ++j) {
            uint32_t off = (uint32_t)row * 128 + part * (KP * 2) + j * 16;
            cpa16(aDst + swz(off), p + j * 8, ok);
        }
        uint32_t bDst = sB0 + s * BBUF;
#pragma unroll
        for (int c = 0; c < 2; ++c) {
            int u = c * T + tid;
            int r = u >> 3, sg = u & 7;
            cpa16(bDst + swz((uint32_t)r * 128 + sg * 16),
                  Bw + (long)r * K + k0 + sg * 8, true);
        }
    };

    fill(0, 0);
    cpa_commit();

    int s = 0;
    for (int k0 = 0; k0 < K; k0 += 64, s ^= 1) {
        if (k0 + 64 < K) {
            fill(k0 + 64, s ^ 1);
            cpa_commit();
            cpa_wait<1>();
        } else {
            cpa_wait<0>();
        }
        __syncthreads();

        const uint32_t aBase = sA0 + s * ABUF;
        const uint32_t bBase = sB0 + s * BBUF;
#pragma unroll
        for (int ks = 0; ks < 4; ++ks) {
            const uint32_t kb = ks * 32 + (lane >> 4) * 16;
            uint32_t af[4][4];
#pragma unroll
            for (int mi = 0; mi < 4; ++mi) {
                uint32_t r = wm + mi * 16 + (lane & 15);
                uint32_t ad = aBase + swz(r * 128 + kb);
                asm volatile("ldmatrix.sync.aligned.m8n8.x4.shared.b16 {%0,%1,%2,%3}, [%4];"
                    : "=r"(af[mi][0]), "=r"(af[mi][1]), "=r"(af[mi][2]), "=r"(af[mi][3])
                    : "r"(ad));
            }
            uint32_t bf[2][4];
#pragma unroll
            for (int ni = 0; ni < 2; ++ni) {
                uint32_t r = wn + ni * 16 + (lane & 15);
                uint32_t ad = bBase + swz(r * 128 + kb);
                asm volatile("ldmatrix.sync.aligned.m8n8.x4.shared.b16 {%0,%1,%2,%3}, [%4];"
                    : "=r"(bf[ni][0]), "=r"(bf[ni][1]), "=r"(bf[ni][2]), "=r"(bf[ni][3])
                    : "r"(ad));
            }
#pragma unroll
            for (int mi = 0; mi < 4; ++mi)
#pragma unroll
                for (int ni = 0; ni < 2; ++ni) {
                    asm volatile(
                        "mma.sync.aligned.m16n8k16.row.col.f32.bf16.bf16.f32 "
                        "{%0,%1,%2,%3}, {%4,%5,%6,%7}, {%8,%9}, {%0,%1,%2,%3};"
                        : "+f"(acc[mi][2*ni][0]), "+f"(acc[mi][2*ni][1]),
                          "+f"(acc[mi][2*ni][2]), "+f"(acc[mi][2*ni][3])
                        : "r"(af[mi][0]), "r"(af[mi][1]), "r"(af[mi][2]), "r"(af[mi][3]),
                          "r"(bf[ni][0]), "r"(bf[ni][2]));
                    asm volatile(
                        "mma.sync.aligned.m16n8k16.row.col.f32.bf16.bf16.f32 "
                        "{%0,%1,%2,%3}, {%4,%5,%6,%7}, {%8,%9}, {%0,%1,%2,%3};"
                        : "+f"(acc[mi][2*ni+1][0]), "+f"(acc[mi][2*ni+1][1]),
                          "+f"(acc[mi][2*ni+1][2]), "+f"(acc[mi][2*ni+1][3])
                        : "r"(af[mi][0]), "r"(af[mi][1]), "r"(af[mi][2]), "r"(af[mi][3]),
                          "r"(bf[ni][1]), "r"(bf[ni][3]));
                }
        }
        __syncthreads();
    }

    const int col = wn + (lane & 3) * 2;
#pragma unroll
    for (int mi = 0; mi < 4; ++mi) {
        int m1 = m0 + wm + mi * 16 + (lane >> 2);
        long b1 = epi_base(ep, m1);
        long b2 = epi_base(ep, m1 + 8);
#pragma unroll
        for (int j = 0; j < 4; ++j) {
            int n = col + j * 8;
            float bi0 = ep.bias[n], bi1 = ep.bias[n + 1];
            float v0 = acc[mi][j][0] + bi0, v1 = acc[mi][j][1] + bi1;
            float v2 = acc[mi][j][2] + bi0, v3 = acc[mi][j][3] + bi1;
            if (ep.act) {
                v0 = fmaxf(v0, 0.f); v1 = fmaxf(v1, 0.f);
                v2 = fmaxf(v2, 0.f); v3 = fmaxf(v3, 0.f);
            }
            if (OBF) {
                __nv_bfloat16* ob = (__nv_bfloat16*)ep.out;
                __nv_bfloat162 p0 = __floats2bfloat162_rn(v0, v1);
                __nv_bfloat162 p1 = __floats2bfloat162_rn(v2, v3);
                *(uint32_t*)(ob + b1 + n) = *(uint32_t*)&p0;
                *(uint32_t*)(ob + b2 + n) = *(uint32_t*)&p1;
            } else {
                *(float2*)(ep.out + b1 + n) = make_float2(v0, v1);
                *(float2*)(ep.out + b2 + n) = make_float2(v2, v3);
            }
        }
    }
}

// ---------------- fused VQ: distances + argmin + gather(bf16) + loss ----------------
__global__ void __launch_bounds__(256)
vq_fused(const float* __restrict__ z, const float* __restrict__ emb,
         const float* __restrict__ enorm, __nv_bfloat16* __restrict__ qb) {
    __shared__ float4 se[16][16];
    __shared__ float sen[16];
    __shared__ float red[256];
    const int t = threadIdx.x;
    const long m = (long)blockIdx.x * 256 + t;
    float4 zr[16];
    const float4* zp = (const float4*)(z + m * 64);
#pragma unroll
    for (int i = 0; i < 16; ++i) zr[i] = zp[i];

    float best = 3.4e38f; int bidx = 0;
    const int ljj = t >> 4, ldd = t & 15;
    for (int j0 = 0; j0 < 512; j0 += 16) {
        __syncthreads();
        se[ljj][ldd] = ((const float4*)(emb + (long)(j0 + ljj) * 64))[ldd];
        if (t < 16) sen[t] = enorm[j0 + t];
        __syncthreads();
#pragma unroll
        for (int jj = 0; jj < 16; ++jj) {
            float s0 = 0.f, s1 = 0.f, s2 = 0.f, s3 = 0.f;
#pragma unroll
            for (int d = 0; d < 16; d += 4) {
                float4 e0 = se[jj][d+0], e1 = se[jj][d+1];
                float4 e2 = se[jj][d+2], e3 = se[jj][d+3];
                s0 = fmaf(zr[d+0].x, e0.x, s0); s0 = fmaf(zr[d+0].y, e0.y, s0);
                s0 = fmaf(zr[d+0].z, e0.z, s0); s0 = fmaf(zr[d+0].w, e0.w, s0);
                s1 = fmaf(zr[d+1].x, e1.x, s1); s1 = fmaf(zr[d+1].y, e1.y, s1);
                s1 = fmaf(zr[d+1].z, e1.z, s1); s1 = fmaf(zr[d+1].w, e1.w, s1);
                s2 = fmaf(zr[d+2].x, e2.x, s2); s2 = fmaf(zr[d+2].y, e2.y, s2);
                s2 = fmaf(zr[d+2].z, e2.z, s2); s2 = fmaf(zr[d+2].w, e2.w, s2);
                s3 = fmaf(zr[d+3].x, e3.x, s3); s3 = fmaf(zr[d+3].y, e3.y, s3);
                s3 = fmaf(zr[d+3].z, e3.z, s3); s3 = fmaf(zr[d+3].w, e3.w, s3);
            }
            float dist = sen[jj] - 2.f * ((s0 + s1) + (s2 + s3));
            if (dist < best) { best = dist; bidx = j0 + jj; }
        }
    }

    const float4* ep = (const float4*)(emb + (long)bidx * 64);
    uint2* qp = (uint2*)(qb + m * 64);
    float sq = 0.f;
#pragma unroll
    for (int i = 0; i < 16; ++i) {
        float4 e = ep[i];
        __nv_bfloat162 p0 = __floats2bfloat162_rn(e.x, e.y);
        __nv_bfloat162 p1 = __floats2bfloat162_rn(e.z, e.w);
        uint2 u; u.x = *(uint32_t*)&p0; u.y = *(uint32_t*)&p1;
        qp[i] = u;
        float d0 = e.x - zr[i].x, d1 = e.y - zr[i].y;
        float d2 = e.z - zr[i].z, d3 = e.w - zr[i].w;
        sq = fmaf(d0, d0, sq); sq = fmaf(d1, d1, sq);
        sq = fmaf(d2, d2, sq); sq = fmaf(d3, d3, sq);
    }
    red[t] = sq;
    __syncthreads();
    for (int s = 128; s; s >>= 1) {
        if (t < s) red[t] += red[t + s];
        __syncthreads();
    }
    if (t == 0) atomicAdd(&g_loss, (double)red[0]);
}

// ---------------- final deconv 64->3 k3 s1 p1 + sigmoid (bf16 in, NCHW fp32 out) ----------------
__global__ void __launch_bounds__(256)
deconv3_sigmoid(const __nv_bfloat16* __restrict__ in, const float* __restrict__ w,
                const float* __restrict__ bias, float* __restrict__ out) {
    __shared__ float sIn[8][18][66];
    __shared__ float sW[1728];
    const int t = threadIdx.x, n = blockIdx.z;
    const int y0 = blockIdx.y * 16, x0 = blockIdx.x * 64;
    for (int i = t; i < 1728; i += 256) sW[i] = w[i];
    const int ty = t >> 4, txq = t & 15;
    float acc[3][4] = {};
    for (int cc = 0; cc < 8; ++cc) {
        __syncthreads();
        for (int idx = t; idx < 8*18*66; idx += 256) {
            int ci = idx & 7, rr = idx >> 3;
            int sx = rr % 66, sy = rr / 66;
            int gy = y0 - 1 + sy, gx = x0 - 1 + sx;
            float v = 0.f;
            if (gy >= 0 && gy < 256 && gx >= 0 && gx < 256)
                v = __bfloat162float(in[(((long)n * 256 + gy) * 256 + gx) * 64 + cc * 8 + ci]);
            sIn[ci][sy][sx] = v;
        }
        __syncthreads();
#pragma unroll
        for (int c8 = 0; c8 < 8; ++c8) {
            const int ci = cc * 8 + c8;
#pragma unroll
            for (int ky = 0; ky < 3; ++ky)
#pragma unroll
            for (int kx = 0; kx < 3; ++kx) {
                const float* wp = &sW[ci*27 + ky*3 + kx];
                float w0 = wp[0], w1 = wp[9], w2 = wp[18];
                const float* ip = &sIn[c8][ty + 2 - ky][txq*4 + 2 - kx];
#pragma unroll
                for (int qq = 0; qq < 4; ++qq) {
                    float iv = ip[qq];
                    acc[0][qq] = fmaf(iv, w0, acc[0][qq]);
                    acc[1][qq] = fmaf(iv, w1, acc[1][qq]);
                    acc[2][qq] = fmaf(iv, w2, acc[2][qq]);
                }
            }
        }
    }
#pragma unroll
    for (int co = 0; co < 3; ++co) {
        float bb = bias[co];
#pragma unroll
        for (int qq = 0; qq < 4; ++qq) {
            float v = acc[co][qq] + bb;
            v = 1.f / (1.f + __expf(-v));
            out[(((long)n * 3 + co) * 256 + (y0 + ty)) * 256 + (x0 + txq*4 + qq)] = v;
        }
    }
}

// ---------------- host ----------------
static float* symaddr(const void* sym) {
    void* p = nullptr;
    cudaGetSymbolAddress(&p, sym);
    return (float*)p;
}

static Epi mk_row(float* out, const float* bias, int ldc, int act) {
    Epi e; e.out = out; e.bias = bias; e.mode = 0; e.act = act; e.ldc = ldc;
    e.MPN = e.OV = e.W2 = e.C = e.py = e.px = 0; e.nstride = 0; return e;
}
static Epi mk_dec(float* out, const float* bias, int MPN, int OV, int W2, int C,
                  int py, int px, long nstride, int act) {
    Epi e; e.out = out; e.bias = bias; e.mode = 1; e.act = act; e.ldc = 0;
    e.MPN = MPN; e.OV = OV; e.W2 = W2; e.C = C; e.py = py; e.px = px;
    e.nstride = nstride; return e;
}

typedef ConvLoaderB<64,4,4,2,1,128,128,64>   LdL2;
typedef ConvLoaderB<128,3,3,1,1,64,64,64>    LdL3;
typedef DeconvLoaderB<64,64,64>              LdD1;
typedef DeconvLoaderB<128,128,128>           LdD2;

extern "C" void kernel_launch(void* const* d_in, const int* in_sizes, int n_in,
                              void* d_out, int out_size) {
    const float* x   = (const float*)d_in[0];
    const float* w1  = (const float*)d_in[1];
    const float* b1  = (const float*)d_in[2];
    const float* w2  = (const float*)d_in[3];
    const float* b2  = (const float*)d_in[4];
    const float* w3  = (const float*)d_in[5];
    const float* b3  = (const float*)d_in[6];
    const float* emb = (const float*)d_in[7];
    const float* dw1 = (const float*)d_in[8];
    const float* db1 = (const float*)d_in[9];
    const float* dw2 = (const float*)d_in[10];
    const float* db2 = (const float*)d_in[11];
    const float* dw3 = (const float*)d_in[12];
    const float* db3 = (const float*)d_in[13];
    float* out = (float*)d_out;

    float* xt  = symaddr(g_xt);
    float* z   = symaddr(g_z);
    float* col = symaddr(g_col);
    float* wb1 = symaddr(g_wb1);
    float* en  = symaddr(g_enorm);
    __nv_bfloat16* h1b = (__nv_bfloat16*)symaddr(g_h1b);
    __nv_bfloat16* h2b = (__nv_bfloat16*)symaddr(g_h2b);
    __nv_bfloat16* qb  = (__nv_bfloat16*)symaddr(g_qb);
    __nv_bfloat16* d1b = (__nv_bfloat16*)symaddr(g_d1b);
    __nv_bfloat16* d2b = (__nv_bfloat16*)symaddr(g_d2b);
    __nv_bfloat16* wb2b = (__nv_bfloat16*)symaddr(g_wb2b);
    __nv_bfloat16* wb3b = (__nv_bfloat16*)symaddr(g_wb3b);
    __nv_bfloat16* wbd  = (__nv_bfloat16*)symaddr(g_wbd);

    const int SM64  = 2 * (256*128 + 64*128);    // 81920
    const int SM128 = 2 * (256*128 + 128*128);   // 98304

    static int attr_done = 0;
    if (!attr_done) {
        cudaFuncSetAttribute((const void*)hgemm2<LdL2,128,true>, cudaFuncAttributeMaxDynamicSharedMemorySize, SM128);
        cudaFuncSetAttribute((const void*)hgemm2<LdL3,64,false>, cudaFuncAttributeMaxDynamicSharedMemorySize, SM64);
        cudaFuncSetAttribute((const void*)hgemm2<LdD1,128,true>, cudaFuncAttributeMaxDynamicSharedMemorySize, SM128);
        cudaFuncSetAttribute((const void*)hgemm2<LdD2,64,true>,  cudaFuncAttributeMaxDynamicSharedMemorySize, SM64);
        attr_done = 1;
    }

    // L1: conv 3->64 k4 s2 p1 (fp32 GEMM, bf16 output)
    nchw_to_nhwc_x<<<8192, 256>>>(x, xt);
    pack_conv_w<<<(64*48+255)/256, 256>>>(w1, wb1, 64, 3, 4, 4);
    im2col_conv<3,4,4,2,1,256,256,128,16,16><<<524288/16, 256>>>(xt, col);
    { DenseLoader ld; ld.A = col; ld.ldk = 48;
      sgemm_t<<<dim3(1, 4096), 256>>>(ld, wb1, 48, mk_row(nullptr, b1, 64, 1), h1b); }

    // L2: conv 64->128 k4 s2 p1, bf16 HMMA v2, bf16 out (M=131072)
    pack_conv_w_bf16<<<(128*1024+255)/256, 256>>>(w2, wb2b, 128, 64, 4, 4);
    { LdL2 ld; ld.in = h1b;
      hgemm2<LdL2,128,true><<<dim3(1, 512), 512, SM128>>>(ld, wb2b, 1024,
          mk_row((float*)h2b, b2, 128, 1)); }

    // L3: conv 128->64 k3 s1 p1, bf16 HMMA v2, fp32 z out
    pack_conv_w_bf16<<<(64*1152+255)/256, 256>>>(w3, wb3b, 64, 128, 3, 3);
    { LdL3 ld; ld.in = h2b;
      hgemm2<LdL3,64,false><<<dim3(1, 512), 256, SM64>>>(ld, wb3b, 1152,
          mk_row(z, b3, 64, 1)); }

    // VQ fused (fp32 math, bf16 q out)
    compute_enorm<<<2, 256>>>(emb, en);
    zero_loss<<<1, 1>>>();
    vq_fused<<<512, 256>>>(z, emb, en, qb);

    // D1: deconv 64->128, 4 parities, bf16 out (M=131072)
    for (int py = 0; py < 2; ++py)
        for (int px = 0; px < 2; ++px) {
            pack_deconv_w_bf16<<<128, 256>>>(dw1, wbd, 64, 128, py, px);
            LdD1 ld; ld.in = qb; ld.py = py; ld.px = px;
            hgemm2<LdD1,128,true><<<dim3(1, 512), 512, SM128>>>(ld, wbd, 256,
                mk_dec((float*)d1b, db1, 64*64, 64, 128, 128, py, px, (long)128*128*128, 1));
        }

    // D2: deconv 128->64, 4 parities, bf16 out (M=524288)
    for (int py = 0; py < 2; ++py)
        for (int px = 0; px < 2; ++px) {
            pack_deconv_w_bf16<<<128, 256>>>(dw2, wbd, 128, 64, py, px);
            LdD2 ld; ld.in = d1b; ld.py = py; ld.px = px;
            hgemm2<LdD2,64,true><<<dim3(1, 2048), 256, SM64>>>(ld, wbd, 512,
                mk_dec((float*)d2b, db2, 128*128, 128, 256, 64, py, px, (long)256*256*64, 1));
        }

    // D3: deconv 64->3 k3 s1 p1 + sigmoid -> NCHW out (fp32)
    deconv3_sigmoid<<<dim3(4, 16, 32), 256>>>(d2b, dw3, db3, out);

    finalize_loss<<<1, 1>>>(out, (long)out_size - 1);
}

// round 10
// speedup vs baseline: 1.6837x; 1.6837x over previous
#include <cuda_runtime.h>
#include <cuda_bf16.h>
#include <cstdint>
#include <math.h>

// ---------------- device scratch ----------------
__device__ __nv_bfloat16 g_h1b[33554432];      // [32,128,128,64] NHWC bf16
__device__ __nv_bfloat16 g_h2b[16777216];      // [32,64,64,128]  NHWC bf16
__device__ float  g_z  [8388608];              // [32,64,64,64] fp32 (VQ/loss path)
__device__ __nv_bfloat16 g_qb [8388608];       // q bf16 (decoder input)
__device__ __nv_bfloat16 g_d1b[67108864];      // [32,128,128,128] bf16
__device__ __nv_bfloat16 g_d2b[134217728];     // [32,256,256,64]  bf16
__device__ float  g_col[25165824];             // L1 im2col (fp32)
__device__ float  g_wb1[64*48];
__device__ __nv_bfloat16 g_wb2b[131072];
__device__ __nv_bfloat16 g_wb3b[73728];
__device__ __nv_bfloat16 g_wbd[32768];
__device__ float  g_enorm[512];
__device__ double g_loss;

__device__ __forceinline__ uint32_t smem_u32(const void* p) {
    uint32_t a;
    asm("{ .reg .u64 t; cvta.to.shared.u64 t, %1; cvt.u32.u64 %0, t; }" : "=r"(a) : "l"(p));
    return a;
}
__device__ __forceinline__ uint32_t swz(uint32_t off) { return off ^ ((off >> 3) & 0x70); }

// ---------------- small kernels ----------------
__global__ void pack_conv_w(const float* __restrict__ w, float* __restrict__ bw,
                            int Cout, int Cin, int KH, int KW) {
    int idx = blockIdx.x * 256 + threadIdx.x;
    int K = Cin * KH * KW;
    if (idx >= Cout * K) return;
    int co = idx / K, rem = idx % K;
    int ci = rem / (KH * KW), r2 = rem % (KH * KW);
    bw[(long)co * K + r2 * Cin + ci] = w[idx];
}

__global__ void pack_conv_w_bf16(const float* __restrict__ w, __nv_bfloat16* __restrict__ bw,
                                 int Cout, int Cin, int KH, int KW) {
    int idx = blockIdx.x * 256 + threadIdx.x;
    int K = Cin * KH * KW;
    if (idx >= Cout * K) return;
    int co = idx / K, rem = idx % K;
    int ci = rem / (KH * KW), r2 = rem % (KH * KW);
    bw[(long)co * K + r2 * Cin + ci] = __float2bfloat16(w[idx]);
}

__global__ void pack_deconv_w_bf16(const float* __restrict__ w, __nv_bfloat16* __restrict__ bw,
                                   int Cin, int Cout, int py, int px) {
    int idx = blockIdx.x * 256 + threadIdx.x;
    if (idx >= Cout * Cin * 4) return;
    int co = idx / (Cin * 4), rem = idx % (Cin * 4);
    int ci = rem / 4, tt = rem % 4;
    int ky = (1 - py) + 2 * (tt >> 1), kx = (1 - px) + 2 * (tt & 1);
    bw[(long)co * (4 * Cin) + tt * Cin + ci] =
        __float2bfloat16(w[(((long)ci * Cout + co) * 4 + ky) * 4 + kx]);
}

__global__ void compute_enorm(const float* __restrict__ emb, float* __restrict__ en) {
    int j = blockIdx.x * 256 + threadIdx.x;
    if (j >= 512) return;
    float s = 0.f;
    const float* e = emb + (long)j * 64;
#pragma unroll 8
    for (int d = 0; d < 64; ++d) { float v = e[d]; s = fmaf(v, v, s); }
    en[j] = s;
}

__global__ void zero_loss() { g_loss = 0.0; }
__global__ void finalize_loss(float* out, long pos) {
    out[pos] = (float)(1.25 * g_loss / 8388608.0);
}

// ---------------- L1 im2col reading x NCHW directly ----------------
__global__ void __launch_bounds__(256)
im2col_l1(const float* __restrict__ x, float* __restrict__ col) {
    // M=524288 (32*128*128), K=48, k=(ky,kx,ci) ci fastest; conv k4 s2 p1
    int mi = threadIdx.x >> 4, kt = threadIdx.x & 15;
    int m = blockIdx.x * 16 + mi;
    int n = m >> 14;
    int r = m & 16383;
    int oy = r >> 7, ox = r & 127;
    const float* xb = x + (long)n * 196608;
    float* colr = col + (long)m * 48;
    for (int k = kt; k < 48; k += 16) {
        int ci = k % 3, t = k / 3;
        int kx = t & 3, ky = t >> 2;
        int iy = oy * 2 - 1 + ky, ix = ox * 2 - 1 + kx;
        float v = 0.f;
        if (iy >= 0 && iy < 256 && ix >= 0 && ix < 256)
            v = xb[((long)ci << 16) + iy * 256 + ix];
        colr[k] = v;
    }
}

// ---------------- A-tile loaders ----------------
struct DenseLoader {
    const float* A; int ldk;
    const float* p;
    __device__ void init(int m) { p = A + (long)m * ldk; }
    __device__ void load8(int k, float4& a0, float4& a1) const {
        a0 = *(const float4*)(p + k);
        a1 = *(const float4*)(p + k + 4);
    }
};

template<int CIN, int KH, int KW, int ST, int PAD, int IH, int IW, int OW>
struct ConvLoaderB {
    const __nv_bfloat16* in;
    const __nv_bfloat16* base; int oy, ox;
    __device__ void init(int m) {
        int n = m / (OW * OW);
        int r = m % (OW * OW);
        oy = r / OW; ox = r % OW;
        base = in + (long)n * IH * IW * CIN;
    }
    __device__ void load32(int k, uint4 (&a)[4]) const {
        int ci = k % CIN, t = k / CIN;
        int ky = t / KW, kx = t % KW;
        int iy = oy * ST - PAD + ky, ix = ox * ST - PAD + kx;
        if (iy >= 0 && iy < IH && ix >= 0 && ix < IW) {
            const uint4* p = (const uint4*)(base + ((long)iy * IW + ix) * CIN + ci);
#pragma unroll
            for (int i = 0; i < 4; ++i) a[i] = p[i];
        } else {
#pragma unroll
            for (int i = 0; i < 4; ++i) a[i] = make_uint4(0,0,0,0);
        }
    }
};

template<int CIN, int IH, int IW>
struct DeconvLoaderB {
    const __nv_bfloat16* in; int py, px;
    const __nv_bfloat16* base; int u, v;
    __device__ void init(int m) {
        int n = m / (IH * IW);
        int r = m % (IH * IW);
        u = r / IW; v = r % IW;
        base = in + (long)n * IH * IW * CIN;
    }
    __device__ void load32(int k, uint4 (&a)[4]) const {
        int ci = k % CIN, t = k / CIN;
        int iy = u + py - (t >> 1), ix = v + px - (t & 1);
        if (iy >= 0 && iy < IH && ix >= 0 && ix < IW) {
            const uint4* p = (const uint4*)(base + ((long)iy * IW + ix) * CIN + ci);
#pragma unroll
            for (int i = 0; i < 4; ++i) a[i] = p[i];
        } else {
#pragma unroll
            for (int i = 0; i < 4; ++i) a[i] = make_uint4(0,0,0,0);
        }
    }
};

// ---------------- epilogue descriptor ----------------
struct Epi {
    float* out; const float* bias;
    int mode, act, ldc;          // mode 0: row-major; 1: deconv NHWC scatter
    int MPN, OV, W2, C, py, px;
    long nstride;
};

__device__ __forceinline__ long epi_base(const Epi& ep, int m) {
    if (ep.mode == 0) return (long)m * ep.ldc;
    int nn = m / ep.MPN, r = m % ep.MPN;
    int u = r / ep.OV, v = r % ep.OV;
    return (long)nn * ep.nstride +
           ((long)(2*u + ep.py) * ep.W2 + (2*v + ep.px)) * ep.C;
}

// ---------------- fp32 SGEMM (L1 only), bf16 output ----------------
template<class LD>
__global__ void __launch_bounds__(256)
sgemm_t(LD ld, const float* __restrict__ Bm, int K, Epi ep, __nv_bfloat16* outb) {
    __shared__ float As[16][132];
    __shared__ float Bs[16][68];
    const int tid = threadIdx.x;
    const int m0 = blockIdx.y * 128, n0 = blockIdx.x * 64;
    const int tx = tid & 15, ty = tid >> 4;
    const int ra = tid >> 1, ca = (tid & 1) * 8;
    const int rb = tid >> 2, cb = (tid & 3) * 4;
    float acc[8][4] = {};
    ld.init(m0 + ra);
    const float* Bptr = Bm + (long)(n0 + rb) * K + cb;

    for (int k0 = 0; k0 < K; k0 += 16) {
        float4 a0, a1;
        ld.load8(k0 + ca, a0, a1);
        float4 b0 = *(const float4*)(Bptr + k0);
        As[ca+0][ra]=a0.x; As[ca+1][ra]=a0.y; As[ca+2][ra]=a0.z; As[ca+3][ra]=a0.w;
        As[ca+4][ra]=a1.x; As[ca+5][ra]=a1.y; As[ca+6][ra]=a1.z; As[ca+7][ra]=a1.w;
        Bs[cb+0][rb]=b0.x; Bs[cb+1][rb]=b0.y; Bs[cb+2][rb]=b0.z; Bs[cb+3][rb]=b0.w;
        __syncthreads();
#pragma unroll
        for (int kk = 0; kk < 16; ++kk) {
            float4 aA = *(const float4*)&As[kk][ty*8];
            float4 aB = *(const float4*)&As[kk][ty*8+4];
            float4 bb = *(const float4*)&Bs[kk][tx*4];
            float av[8] = {aA.x,aA.y,aA.z,aA.w,aB.x,aB.y,aB.z,aB.w};
            float bv[4] = {bb.x,bb.y,bb.z,bb.w};
#pragma unroll
            for (int i = 0; i < 8; ++i)
#pragma unroll
                for (int j = 0; j < 4; ++j)
                    acc[i][j] = fmaf(av[i], bv[j], acc[i][j]);
        }
        __syncthreads();
    }

    const int n_base = n0 + tx * 4;
    float bvals[4];
#pragma unroll
    for (int j = 0; j < 4; ++j) bvals[j] = ep.bias ? ep.bias[n_base + j] : 0.f;
#pragma unroll
    for (int i = 0; i < 8; ++i) {
        int m = m0 + ty * 8 + i;
        long base = (long)m * ep.ldc + n_base;
        float v0 = fmaxf(acc[i][0] + bvals[0], 0.f);
        float v1 = fmaxf(acc[i][1] + bvals[1], 0.f);
        float v2 = fmaxf(acc[i][2] + bvals[2], 0.f);
        float v3 = fmaxf(acc[i][3] + bvals[3], 0.f);
        __nv_bfloat162 p0 = __floats2bfloat162_rn(v0, v1);
        __nv_bfloat162 p1 = __floats2bfloat162_rn(v2, v3);
        uint2 u; u.x = *(uint32_t*)&p0; u.y = *(uint32_t*)&p1;
        *(uint2*)(outb + base) = u;
    }
}

// ---------------- HMMA bf16 GEMM, double-buffered (R8 design) ----------------
// Block 128 x TN, 8 warps 4(m) x 2(n); K-chunk 64, 2-stage smem, bf16 in, fp32/bf16 out.
template<class LD, int TN, bool OBF>
__global__ void __launch_bounds__(256)
hgemm(LD ld, const __nv_bfloat16* __restrict__ Bw, int K, Epi ep) {
    constexpr int WN  = TN / 2;
    constexpr int NT8 = WN / 8;
    constexpr int NT16 = NT8 / 2;
    constexpr int NB = TN * 8 / 256;
    constexpr uint32_t ABUF = 128 * 64 * 2;
    constexpr uint32_t BBUF = TN * 64 * 2;
    extern __shared__ char dynsm[];
    char* sAp = dynsm;
    char* sBp = dynsm + 2 * ABUF;

    const int tid = threadIdx.x;
    const int wid = tid >> 5, lane = tid & 31;
    const int m0 = blockIdx.y * 128;
    const int wm = (wid >> 1) * 32;
    const int wn = (wid & 1) * WN;
    const uint32_t sA0 = smem_u32(sAp), sB0 = smem_u32(sBp);

    const int row = tid >> 1, half = tid & 1;
    ld.init(m0 + row);

    float acc[2][NT8][4];
#pragma unroll
    for (int i = 0; i < 2; ++i)
#pragma unroll
        for (int j = 0; j < NT8; ++j)
#pragma unroll
            for (int c = 0; c < 4; ++c) acc[i][j][c] = 0.f;

    uint4 a[4];
    uint4 breg[NB];
    ld.load32(half * 32, a);
#pragma unroll
    for (int c = 0; c < NB; ++c) {
        int i = c * 256 + tid;
        breg[c] = *(const uint4*)(Bw + (long)(i >> 3) * K + (i & 7) * 8);
    }

    int s = 0;
    for (int k0 = 0; k0 < K; k0 += 64, s ^= 1) {
        char* aDst = sAp + s * ABUF;
        char* bDst = sBp + s * BBUF;
#pragma unroll
        for (int j = 0; j < 4; ++j) {
            uint32_t off = row * 128 + half * 64 + j * 16;
            *(uint4*)(aDst + swz(off)) = a[j];
        }
#pragma unroll
        for (int c = 0; c < NB; ++c) {
            int i = c * 256 + tid;
            uint32_t off = (uint32_t)(i >> 3) * 128 + (i & 7) * 16;
            *(uint4*)(bDst + swz(off)) = breg[c];
        }
        __syncthreads();

        if (k0 + 64 < K) {
            ld.load32(k0 + 64 + half * 32, a);
#pragma unroll
            for (int c = 0; c < NB; ++c) {
                int i = c * 256 + tid;
                breg[c] = *(const uint4*)(Bw + (long)(i >> 3) * K + k0 + 64 + (i & 7) * 8);
            }
        }

        const uint32_t aBase = sA0 + s * ABUF;
        const uint32_t bBase = sB0 + s * BBUF;
#pragma unroll
        for (int ks = 0; ks < 4; ++ks) {
            uint32_t af[2][4];
#pragma unroll
            for (int mi = 0; mi < 2; ++mi) {
                uint32_t r = wm + mi * 16 + (lane & 15);
                uint32_t kb = ks * 32 + (lane >> 4) * 16;
                uint32_t ad = aBase + swz(r * 128 + kb);
                asm volatile("ldmatrix.sync.aligned.m8n8.x4.shared.b16 {%0,%1,%2,%3}, [%4];"
                    : "=r"(af[mi][0]), "=r"(af[mi][1]), "=r"(af[mi][2]), "=r"(af[mi][3])
                    : "r"(ad));
            }
            uint32_t bf[NT16][4];
#pragma unroll
            for (int ni = 0; ni < NT16; ++ni) {
                uint32_t r = wn + ni * 16 + (lane & 15);
                uint32_t kb = ks * 32 + (lane >> 4) * 16;
                uint32_t ad = bBase + swz(r * 128 + kb);
                asm volatile("ldmatrix.sync.aligned.m8n8.x4.shared.b16 {%0,%1,%2,%3}, [%4];"
                    : "=r"(bf[ni][0]), "=r"(bf[ni][1]), "=r"(bf[ni][2]), "=r"(bf[ni][3])
                    : "r"(ad));
            }
#pragma unroll
            for (int mi = 0; mi < 2; ++mi)
#pragma unroll
                for (int ni = 0; ni < NT16; ++ni) {
                    asm volatile(
                        "mma.sync.aligned.m16n8k16.row.col.f32.bf16.bf16.f32 "
                        "{%0,%1,%2,%3}, {%4,%5,%6,%7}, {%8,%9}, {%0,%1,%2,%3};"
                        : "+f"(acc[mi][2*ni][0]), "+f"(acc[mi][2*ni][1]),
                          "+f"(acc[mi][2*ni][2]), "+f"(acc[mi][2*ni][3])
                        : "r"(af[mi][0]), "r"(af[mi][1]), "r"(af[mi][2]), "r"(af[mi][3]),
                          "r"(bf[ni][0]), "r"(bf[ni][2]));
                    asm volatile(
                        "mma.sync.aligned.m16n8k16.row.col.f32.bf16.bf16.f32 "
                        "{%0,%1,%2,%3}, {%4,%5,%6,%7}, {%8,%9}, {%0,%1,%2,%3};"
                        : "+f"(acc[mi][2*ni+1][0]), "+f"(acc[mi][2*ni+1][1]),
                          "+f"(acc[mi][2*ni+1][2]), "+f"(acc[mi][2*ni+1][3])
                        : "r"(af[mi][0]), "r"(af[mi][1]), "r"(af[mi][2]), "r"(af[mi][3]),
                          "r"(bf[ni][1]), "r"(bf[ni][3]));
                }
        }
        __syncthreads();
    }

    const int col = wn + (lane & 3) * 2;
#pragma unroll
    for (int mi = 0; mi < 2; ++mi) {
        int m1 = m0 + wm + mi * 16 + (lane >> 2);
        long b1 = epi_base(ep, m1);
        long b2 = epi_base(ep, m1 + 8);
#pragma unroll
        for (int j = 0; j < NT8; ++j) {
            int n = col + j * 8;
            float bi0 = ep.bias[n], bi1 = ep.bias[n + 1];
            float v0 = acc[mi][j][0] + bi0, v1 = acc[mi][j][1] + bi1;
            float v2 = acc[mi][j][2] + bi0, v3 = acc[mi][j][3] + bi1;
            if (ep.act) {
                v0 = fmaxf(v0, 0.f); v1 = fmaxf(v1, 0.f);
                v2 = fmaxf(v2, 0.f); v3 = fmaxf(v3, 0.f);
            }
            if (OBF) {
                __nv_bfloat16* ob = (__nv_bfloat16*)ep.out;
                __nv_bfloat162 p0 = __floats2bfloat162_rn(v0, v1);
                __nv_bfloat162 p1 = __floats2bfloat162_rn(v2, v3);
                *(uint32_t*)(ob + b1 + n) = *(uint32_t*)&p0;
                *(uint32_t*)(ob + b2 + n) = *(uint32_t*)&p1;
            } else {
                *(float2*)(ep.out + b1 + n) = make_float2(v0, v1);
                *(float2*)(ep.out + b2 + n) = make_float2(v2, v3);
            }
        }
    }
}

// ---------------- fused VQ: distances + argmin + gather(bf16) + loss ----------------
__global__ void __launch_bounds__(256)
vq_fused(const float* __restrict__ z, const float* __restrict__ emb,
         const float* __restrict__ enorm, __nv_bfloat16* __restrict__ qb) {
    __shared__ float4 se[16][16];
    __shared__ float sen[16];
    __shared__ float red[256];
    const int t = threadIdx.x;
    const long m = (long)blockIdx.x * 256 + t;
    float4 zr[16];
    const float4* zp = (const float4*)(z + m * 64);
#pragma unroll
    for (int i = 0; i < 16; ++i) zr[i] = zp[i];

    float best = 3.4e38f; int bidx = 0;
    const int ljj = t >> 4, ldd = t & 15;
    for (int j0 = 0; j0 < 512; j0 += 16) {
        __syncthreads();
        se[ljj][ldd] = ((const float4*)(emb + (long)(j0 + ljj) * 64))[ldd];
        if (t < 16) sen[t] = enorm[j0 + t];
        __syncthreads();
#pragma unroll
        for (int jj = 0; jj < 16; ++jj) {
            float s0 = 0.f, s1 = 0.f, s2 = 0.f, s3 = 0.f;
#pragma unroll
            for (int d = 0; d < 16; d += 4) {
                float4 e0 = se[jj][d+0], e1 = se[jj][d+1];
                float4 e2 = se[jj][d+2], e3 = se[jj][d+3];
                s0 = fmaf(zr[d+0].x, e0.x, s0); s0 = fmaf(zr[d+0].y, e0.y, s0);
                s0 = fmaf(zr[d+0].z, e0.z, s0); s0 = fmaf(zr[d+0].w, e0.w, s0);
                s1 = fmaf(zr[d+1].x, e1.x, s1); s1 = fmaf(zr[d+1].y, e1.y, s1);
                s1 = fmaf(zr[d+1].z, e1.z, s1); s1 = fmaf(zr[d+1].w, e1.w, s1);
                s2 = fmaf(zr[d+2].x, e2.x, s2); s2 = fmaf(zr[d+2].y, e2.y, s2);
                s2 = fmaf(zr[d+2].z, e2.z, s2); s2 = fmaf(zr[d+2].w, e2.w, s2);
                s3 = fmaf(zr[d+3].x, e3.x, s3); s3 = fmaf(zr[d+3].y, e3.y, s3);
                s3 = fmaf(zr[d+3].z, e3.z, s3); s3 = fmaf(zr[d+3].w, e3.w, s3);
            }
            float dist = sen[jj] - 2.f * ((s0 + s1) + (s2 + s3));
            if (dist < best) { best = dist; bidx = j0 + jj; }
        }
    }

    const float4* ep = (const float4*)(emb + (long)bidx * 64);
    uint2* qp = (uint2*)(qb + m * 64);
    float sq = 0.f;
#pragma unroll
    for (int i = 0; i < 16; ++i) {
        float4 e = ep[i];
        __nv_bfloat162 p0 = __floats2bfloat162_rn(e.x, e.y);
        __nv_bfloat162 p1 = __floats2bfloat162_rn(e.z, e.w);
        uint2 u; u.x = *(uint32_t*)&p0; u.y = *(uint32_t*)&p1;
        qp[i] = u;
        float d0 = e.x - zr[i].x, d1 = e.y - zr[i].y;
        float d2 = e.z - zr[i].z, d3 = e.w - zr[i].w;
        sq = fmaf(d0, d0, sq); sq = fmaf(d1, d1, sq);
        sq = fmaf(d2, d2, sq); sq = fmaf(d3, d3, sq);
    }
    red[t] = sq;
    __syncthreads();
    for (int s = 128; s; s >>= 1) {
        if (t < s) red[t] += red[t + s];
        __syncthreads();
    }
    if (t == 0) atomicAdd(&g_loss, (double)red[0]);
}

// ---------------- final deconv 64->3 k3 s1 p1 + sigmoid (bf16 in, NCHW fp32 out) ----------------
__global__ void __launch_bounds__(256)
deconv3_sigmoid(const __nv_bfloat16* __restrict__ in, const float* __restrict__ w,
                const float* __restrict__ bias, float* __restrict__ out) {
    __shared__ float sIn[8][18][66];
    __shared__ float sW[1728];
    const int t = threadIdx.x, n = blockIdx.z;
    const int y0 = blockIdx.y * 16, x0 = blockIdx.x * 64;
    for (int i = t; i < 1728; i += 256) sW[i] = w[i];
    const int ty = t >> 4, txq = t & 15;
    float acc[3][4] = {};
    for (int cc = 0; cc < 8; ++cc) {
        __syncthreads();
        for (int pos = t; pos < 18 * 66; pos += 256) {
            int sx = pos % 66, sy = pos / 66;
            int gy = y0 - 1 + sy, gx = x0 - 1 + sx;
            if (gy >= 0 && gy < 256 && gx >= 0 && gx < 256) {
                uint4 u = *(const uint4*)(in + (((long)n * 256 + gy) * 256 + gx) * 64 + cc * 8);
                float2 f0 = __bfloat1622float2(*(__nv_bfloat162*)&u.x);
                float2 f1 = __bfloat1622float2(*(__nv_bfloat162*)&u.y);
                float2 f2 = __bfloat1622float2(*(__nv_bfloat162*)&u.z);
                float2 f3 = __bfloat1622float2(*(__nv_bfloat162*)&u.w);
                sIn[0][sy][sx] = f0.x; sIn[1][sy][sx] = f0.y;
                sIn[2][sy][sx] = f1.x; sIn[3][sy][sx] = f1.y;
                sIn[4][sy][sx] = f2.x; sIn[5][sy][sx] = f2.y;
                sIn[6][sy][sx] = f3.x; sIn[7][sy][sx] = f3.y;
            } else {
#pragma unroll
                for (int c = 0; c < 8; ++c) sIn[c][sy][sx] = 0.f;
            }
        }
        __syncthreads();
#pragma unroll
        for (int c8 = 0; c8 < 8; ++c8) {
            const int ci = cc * 8 + c8;
#pragma unroll
            for (int ky = 0; ky < 3; ++ky)
#pragma unroll
            for (int kx = 0; kx < 3; ++kx) {
                const float* wp = &sW[ci*27 + ky*3 + kx];
                float w0 = wp[0], w1 = wp[9], w2 = wp[18];
                const float* ip = &sIn[c8][ty + 2 - ky][txq*4 + 2 - kx];
#pragma unroll
                for (int qq = 0; qq < 4; ++qq) {
                    float iv = ip[qq];
                    acc[0][qq] = fmaf(iv, w0, acc[0][qq]);
                    acc[1][qq] = fmaf(iv, w1, acc[1][qq]);
                    acc[2][qq] = fmaf(iv, w2, acc[2][qq]);
                }
            }
        }
    }
#pragma unroll
    for (int co = 0; co < 3; ++co) {
        float bb = bias[co];
#pragma unroll
        for (int qq = 0; qq < 4; ++qq) {
            float v = acc[co][qq] + bb;
            v = 1.f / (1.f + __expf(-v));
            out[(((long)n * 3 + co) * 256 + (y0 + ty)) * 256 + (x0 + txq*4 + qq)] = v;
        }
    }
}

// ---------------- host ----------------
static float* symaddr(const void* sym) {
    void* p = nullptr;
    cudaGetSymbolAddress(&p, sym);
    return (float*)p;
}

static Epi mk_row(float* out, const float* bias, int ldc, int act) {
    Epi e; e.out = out; e.bias = bias; e.mode = 0; e.act = act; e.ldc = ldc;
    e.MPN = e.OV = e.W2 = e.C = e.py = e.px = 0; e.nstride = 0; return e;
}
static Epi mk_dec(float* out, const float* bias, int MPN, int OV, int W2, int C,
                  int py, int px, long nstride, int act) {
    Epi e; e.out = out; e.bias = bias; e.mode = 1; e.act = act; e.ldc = 0;
    e.MPN = MPN; e.OV = OV; e.W2 = W2; e.C = C; e.py = py; e.px = px;
    e.nstride = nstride; return e;
}

typedef ConvLoaderB<64,4,4,2,1,128,128,64>   LdL2;
typedef ConvLoaderB<128,3,3,1,1,64,64,64>    LdL3;
typedef DeconvLoaderB<64,64,64>              LdD1;
typedef DeconvLoaderB<128,128,128>           LdD2;

extern "C" void kernel_launch(void* const* d_in, const int* in_sizes, int n_in,
                              void* d_out, int out_size) {
    const float* x   = (const float*)d_in[0];
    const float* w1  = (const float*)d_in[1];
    const float* b1  = (const float*)d_in[2];
    const float* w2  = (const float*)d_in[3];
    const float* b2  = (const float*)d_in[4];
    const float* w3  = (const float*)d_in[5];
    const float* b3  = (const float*)d_in[6];
    const float* emb = (const float*)d_in[7];
    const float* dw1 = (const float*)d_in[8];
    const float* db1 = (const float*)d_in[9];
    const float* dw2 = (const float*)d_in[10];
    const float* db2 = (const float*)d_in[11];
    const float* dw3 = (const float*)d_in[12];
    const float* db3 = (const float*)d_in[13];
    float* out = (float*)d_out;

    float* z   = symaddr(g_z);
    float* col = symaddr(g_col);
    float* wb1 = symaddr(g_wb1);
    float* en  = symaddr(g_enorm);
    __nv_bfloat16* h1b = (__nv_bfloat16*)symaddr(g_h1b);
    __nv_bfloat16* h2b = (__nv_bfloat16*)symaddr(g_h2b);
    __nv_bfloat16* qb  = (__nv_bfloat16*)symaddr(g_qb);
    __nv_bfloat16* d1b = (__nv_bfloat16*)symaddr(g_d1b);
    __nv_bfloat16* d2b = (__nv_bfloat16*)symaddr(g_d2b);
    __nv_bfloat16* wb2b = (__nv_bfloat16*)symaddr(g_wb2b);
    __nv_bfloat16* wb3b = (__nv_bfloat16*)symaddr(g_wb3b);
    __nv_bfloat16* wbd  = (__nv_bfloat16*)symaddr(g_wbd);

    static int attr_done = 0;
    if (!attr_done) {
        cudaFuncSetAttribute((const void*)hgemm<LdL2,128,true>, cudaFuncAttributeMaxDynamicSharedMemorySize, 65536);
        cudaFuncSetAttribute((const void*)hgemm<LdL3,64,false>, cudaFuncAttributeMaxDynamicSharedMemorySize, 65536);
        cudaFuncSetAttribute((const void*)hgemm<LdD1,128,true>, cudaFuncAttributeMaxDynamicSharedMemorySize, 65536);
        cudaFuncSetAttribute((const void*)hgemm<LdD2,64,true>,  cudaFuncAttributeMaxDynamicSharedMemorySize, 65536);
        attr_done = 1;
    }

    // Launch order arranged so launch #6 (ncu -s 5 -c 1) is hgemm<LdL2,128>.
    // L1: conv 3->64 k4 s2 p1 (NCHW-direct im2col + fp32 GEMM, bf16 out)
    im2col_l1<<<32768, 256>>>(x, col);                                    // 1
    pack_conv_w<<<(64*48+255)/256, 256>>>(w1, wb1, 64, 3, 4, 4);          // 2
    { DenseLoader ld; ld.A = col; ld.ldk = 48;
      sgemm_t<<<dim3(1, 4096), 256>>>(ld, wb1, 48,
          mk_row(nullptr, b1, 64, 1), h1b); }                             // 3
    pack_conv_w_bf16<<<(128*1024+255)/256, 256>>>(w2, wb2b, 128, 64, 4, 4); // 4
    zero_loss<<<1, 1>>>();                                                // 5

    // L2: conv 64->128 k4 s2 p1, bf16 HMMA, bf16 out  (launch #6 - profiled)
    { LdL2 ld; ld.in = h1b;
      hgemm<LdL2,128,true><<<dim3(1, 1024), 256, 65536>>>(ld, wb2b, 1024,
          mk_row((float*)h2b, b2, 128, 1)); }                             // 6

    // L3: conv 128->64 k3 s1 p1, bf16 HMMA, fp32 z out
    pack_conv_w_bf16<<<(64*1152+255)/256, 256>>>(w3, wb3b, 64, 128, 3, 3);
    { LdL3 ld; ld.in = h2b;
      hgemm<LdL3,64,false><<<dim3(1, 1024), 256, 49152>>>(ld, wb3b, 1152,
          mk_row(z, b3, 64, 1)); }

    // VQ fused (fp32 math, bf16 q out)
    compute_enorm<<<2, 256>>>(emb, en);
    vq_fused<<<512, 256>>>(z, emb, en, qb);

    // D1: deconv 64->128, 4 parities, bf16 out
    for (int py = 0; py < 2; ++py)
        for (int px = 0; px < 2; ++px) {
            pack_deconv_w_bf16<<<128, 256>>>(dw1, wbd, 64, 128, py, px);
            LdD1 ld; ld.in = qb; ld.py = py; ld.px = px;
            hgemm<LdD1,128,true><<<dim3(1, 1024), 256, 65536>>>(ld, wbd, 256,
                mk_dec((float*)d1b, db1, 64*64, 64, 128, 128, py, px, (long)128*128*128, 1));
        }

    // D2: deconv 128->64, 4 parities, bf16 out
    for (int py = 0; py < 2; ++py)
        for (int px = 0; px < 2; ++px) {
            pack_deconv_w_bf16<<<128, 256>>>(dw2, wbd, 128, 64, py, px);
            LdD2 ld; ld.in = d1b; ld.py = py; ld.px = px;
            hgemm<LdD2,64,true><<<dim3(1, 4096), 256, 49152>>>(ld, wbd, 512,
                mk_dec((float*)d2b, db2, 128*128, 128, 256, 64, py, px, (long)256*256*64, 1));
        }

    // D3: deconv 64->3 k3 s1 p1 + sigmoid -> NCHW out (fp32)
    deconv3_sigmoid<<<dim3(4, 16, 32), 256>>>(d2b, dw3, db3, out);

    finalize_loss<<<1, 1>>>(out, (long)out_size - 1);
}

// round 11
// speedup vs baseline: 1.9360x; 1.1498x over previous
#include <cuda_runtime.h>
#include <cuda_bf16.h>
#include <cstdint>
#include <math.h>

// ---------------- device scratch ----------------
__device__ __nv_bfloat16 g_h1b[33554432];      // [32,128,128,64] NHWC bf16
__device__ __nv_bfloat16 g_h2b[16777216];      // [32,64,64,128]  NHWC bf16
__device__ float  g_z  [8388608];              // [32,64,64,64] fp32 (VQ/loss path)
__device__ __nv_bfloat16 g_qb [8388608];       // q bf16 (decoder input)
__device__ __nv_bfloat16 g_d1b[67108864];      // [32,128,128,128] bf16
__device__ __nv_bfloat16 g_d2b[134217728];     // [32,256,256,64]  bf16
__device__ float  g_col[25165824];             // L1 im2col (fp32)
__device__ float  g_wb1[3072];
__device__ __nv_bfloat16 g_wb2b[131072];
__device__ __nv_bfloat16 g_wb3b[73728];
__device__ __nv_bfloat16 g_wbd1[131072];       // 4 parities x 32768
__device__ __nv_bfloat16 g_wbd2[131072];       // 4 parities x 32768
__device__ float  g_enorm[512];
__device__ double g_loss;

__device__ __forceinline__ uint32_t smem_u32(const void* p) {
    uint32_t a;
    asm("{ .reg .u64 t; cvta.to.shared.u64 t, %1; cvt.u32.u64 %0, t; }" : "=r"(a) : "l"(p));
    return a;
}
__device__ __forceinline__ uint32_t swz(uint32_t off) { return off ^ ((off >> 3) & 0x70); }
__device__ __forceinline__ void cpa16(uint32_t dst, const void* src, bool ok) {
    asm volatile("cp.async.cg.shared.global [%0], [%1], 16, %2;"
                 :: "r"(dst), "l"(src), "r"(ok ? 16 : 0) : "memory");
}
__device__ __forceinline__ void cpa_commit() {
    asm volatile("cp.async.commit_group;" ::: "memory");
}
template<int N>
__device__ __forceinline__ void cpa_wait() {
    asm volatile("cp.async.wait_group %0;" :: "n"(N) : "memory");
}

// ---------------- pack_all: every weight pack + enorm + loss zero, one launch ----------------
__global__ void __launch_bounds__(256)
pack_all(const float* __restrict__ w1, const float* __restrict__ w2,
         const float* __restrict__ w3, const float* __restrict__ dw1,
         const float* __restrict__ dw2, const float* __restrict__ emb) {
    long idx = (long)blockIdx.x * 256 + threadIdx.x;
    if (idx < 3072) {                           // wb1: Cout=64,Cin=3,k4x4
        int co = (int)idx / 48, rem = (int)idx % 48;
        int ci = rem / 16, r2 = rem % 16;
        g_wb1[co * 48 + r2 * 3 + ci] = w1[idx];
        return;
    }
    idx -= 3072;
    if (idx < 131072) {                          // wb2b: Cout=128,Cin=64,k4x4
        int co = (int)idx >> 10, rem = (int)idx & 1023;
        int ci = rem >> 4, r2 = rem & 15;
        g_wb2b[co * 1024 + r2 * 64 + ci] = __float2bfloat16(w2[idx]);
        return;
    }
    idx -= 131072;
    if (idx < 73728) {                           // wb3b: Cout=64,Cin=128,k3x3
        int co = (int)idx / 1152, rem = (int)idx % 1152;
        int ci = rem / 9, r2 = rem % 9;
        g_wb3b[co * 1152 + r2 * 128 + ci] = __float2bfloat16(w3[idx]);
        return;
    }
    idx -= 73728;
    if (idx < 131072) {                          // wbd1: 4 parities, Cin=64,Cout=128
        int p = (int)idx >> 15, local = (int)idx & 32767;
        int py = p >> 1, px = p & 1;
        int co = local >> 8, rem = local & 255;
        int ci = rem >> 2, tt = rem & 3;
        int ky = (1 - py) + 2 * (tt >> 1), kx = (1 - px) + 2 * (tt & 1);
        g_wbd1[p * 32768 + co * 256 + tt * 64 + ci] =
            __float2bfloat16(dw1[(((long)ci * 128 + co) * 4 + ky) * 4 + kx]);
        return;
    }
    idx -= 131072;
    if (idx < 131072) {                          // wbd2: 4 parities, Cin=128,Cout=64
        int p = (int)idx >> 15, local = (int)idx & 32767;
        int py = p >> 1, px = p & 1;
        int co = local >> 9, rem = local & 511;
        int ci = rem >> 2, tt = rem & 3;
        int ky = (1 - py) + 2 * (tt >> 1), kx = (1 - px) + 2 * (tt & 1);
        g_wbd2[p * 32768 + co * 512 + tt * 128 + ci] =
            __float2bfloat16(dw2[(((long)ci * 64 + co) * 4 + ky) * 4 + kx]);
        return;
    }
    idx -= 131072;
    if (idx < 512) {                             // enorm
        float s = 0.f;
        const float* e = emb + idx * 64;
#pragma unroll 8
        for (int d = 0; d < 64; ++d) { float v = e[d]; s = fmaf(v, v, s); }
        g_enorm[idx] = s;
        return;
    }
    if (idx == 512) g_loss = 0.0;
}

__global__ void finalize_loss(float* out, long pos) {
    out[pos] = (float)(1.25 * g_loss / 8388608.0);
}

// ---------------- L1 im2col reading x NCHW directly ----------------
__global__ void __launch_bounds__(256)
im2col_l1(const float* __restrict__ x, float* __restrict__ col) {
    int mi = threadIdx.x >> 4, kt = threadIdx.x & 15;
    int m = blockIdx.x * 16 + mi;
    int n = m >> 14;
    int r = m & 16383;
    int oy = r >> 7, ox = r & 127;
    const float* xb = x + (long)n * 196608;
    float* colr = col + (long)m * 48;
    for (int k = kt; k < 48; k += 16) {
        int ci = k % 3, t = k / 3;
        int kx = t & 3, ky = t >> 2;
        int iy = oy * 2 - 1 + ky, ix = ox * 2 - 1 + kx;
        float v = 0.f;
        if (iy >= 0 && iy < 256 && ix >= 0 && ix < 256)
            v = xb[((long)ci << 16) + iy * 256 + ix];
        colr[k] = v;
    }
}

// ---------------- A-tile loaders ----------------
struct DenseLoader {
    const float* A; int ldk;
    const float* p;
    __device__ void init(int m) { p = A + (long)m * ldk; }
    __device__ void load8(int k, float4& a0, float4& a1) const {
        a0 = *(const float4*)(p + k);
        a1 = *(const float4*)(p + k + 4);
    }
};

// addr() of a 32-k segment; segment stays inside one (ky,kx) tap (CIN%32==0).
template<int CIN, int KH, int KW, int ST, int PAD, int IH, int IW, int OW>
struct ConvLoaderB {
    const __nv_bfloat16* in;
    const __nv_bfloat16* base; int oy, ox;
    __device__ void init(int m) {
        int n = m / (OW * OW);
        int r = m % (OW * OW);
        oy = r / OW; ox = r % OW;
        base = in + (long)n * IH * IW * CIN;
    }
    __device__ const __nv_bfloat16* addr(int k, bool& ok) const {
        int ci = k % CIN, t = k / CIN;
        int ky = t / KW, kx = t % KW;
        int iy = oy * ST - PAD + ky, ix = ox * ST - PAD + kx;
        ok = (iy >= 0 && iy < IH && ix >= 0 && ix < IW);
        return ok ? base + ((long)iy * IW + ix) * CIN + ci : base;
    }
};

template<int CIN, int IH, int IW>
struct DeconvLoaderB {
    const __nv_bfloat16* in; int py, px;
    const __nv_bfloat16* base; int u, v;
    __device__ void init(int m) {
        int n = m / (IH * IW);
        int r = m % (IH * IW);
        u = r / IW; v = r % IW;
        base = in + (long)n * IH * IW * CIN;
    }
    __device__ const __nv_bfloat16* addr(int k, bool& ok) const {
        int ci = k % CIN, t = k / CIN;
        int iy = u + py - (t >> 1), ix = v + px - (t & 1);
        ok = (iy >= 0 && iy < IH && ix >= 0 && ix < IW);
        return ok ? base + ((long)iy * IW + ix) * CIN + ci : base;
    }
};

// ---------------- epilogue descriptor ----------------
struct Epi {
    float* out; const float* bias;
    int mode, act, ldc;
    int MPN, OV, W2, C, py, px;
    long nstride;
};

__device__ __forceinline__ long epi_base(const Epi& ep, int m) {
    if (ep.mode == 0) return (long)m * ep.ldc;
    int nn = m / ep.MPN, r = m % ep.MPN;
    int u = r / ep.OV, v = r % ep.OV;
    return (long)nn * ep.nstride +
           ((long)(2*u + ep.py) * ep.W2 + (2*v + ep.px)) * ep.C;
}

// ---------------- fp32 SGEMM (L1 only), bf16 output ----------------
template<class LD>
__global__ void __launch_bounds__(256)
sgemm_t(LD ld, const float* __restrict__ Bm, int K, Epi ep, __nv_bfloat16* outb) {
    __shared__ float As[16][132];
    __shared__ float Bs[16][68];
    const int tid = threadIdx.x;
    const int m0 = blockIdx.y * 128, n0 = blockIdx.x * 64;
    const int tx = tid & 15, ty = tid >> 4;
    const int ra = tid >> 1, ca = (tid & 1) * 8;
    const int rb = tid >> 2, cb = (tid & 3) * 4;
    float acc[8][4] = {};
    ld.init(m0 + ra);
    const float* Bptr = Bm + (long)(n0 + rb) * K + cb;

    for (int k0 = 0; k0 < K; k0 += 16) {
        float4 a0, a1;
        ld.load8(k0 + ca, a0, a1);
        float4 b0 = *(const float4*)(Bptr + k0);
        As[ca+0][ra]=a0.x; As[ca+1][ra]=a0.y; As[ca+2][ra]=a0.z; As[ca+3][ra]=a0.w;
        As[ca+4][ra]=a1.x; As[ca+5][ra]=a1.y; As[ca+6][ra]=a1.z; As[ca+7][ra]=a1.w;
        Bs[cb+0][rb]=b0.x; Bs[cb+1][rb]=b0.y; Bs[cb+2][rb]=b0.z; Bs[cb+3][rb]=b0.w;
        __syncthreads();
#pragma unroll
        for (int kk = 0; kk < 16; ++kk) {
            float4 aA = *(const float4*)&As[kk][ty*8];
            float4 aB = *(const float4*)&As[kk][ty*8+4];
            float4 bb = *(const float4*)&Bs[kk][tx*4];
            float av[8] = {aA.x,aA.y,aA.z,aA.w,aB.x,aB.y,aB.z,aB.w};
            float bv[4] = {bb.x,bb.y,bb.z,bb.w};
#pragma unroll
            for (int i = 0; i < 8; ++i)
#pragma unroll
                for (int j = 0; j < 4; ++j)
                    acc[i][j] = fmaf(av[i], bv[j], acc[i][j]);
        }
        __syncthreads();
    }

    const int n_base = n0 + tx * 4;
    float bvals[4];
#pragma unroll
    for (int j = 0; j < 4; ++j) bvals[j] = ep.bias ? ep.bias[n_base + j] : 0.f;
#pragma unroll
    for (int i = 0; i < 8; ++i) {
        int m = m0 + ty * 8 + i;
        long base = (long)m * ep.ldc + n_base;
        float v0 = fmaxf(acc[i][0] + bvals[0], 0.f);
        float v1 = fmaxf(acc[i][1] + bvals[1], 0.f);
        float v2 = fmaxf(acc[i][2] + bvals[2], 0.f);
        float v3 = fmaxf(acc[i][3] + bvals[3], 0.f);
        __nv_bfloat162 p0 = __floats2bfloat162_rn(v0, v1);
        __nv_bfloat162 p1 = __floats2bfloat162_rn(v2, v3);
        uint2 u; u.x = *(uint32_t*)&p0; u.y = *(uint32_t*)&p1;
        *(uint2*)(outb + base) = u;
    }
}

// ---------------- HMMA bf16 GEMM, 3-stage cp.async (128 x TN, 8 warps) ----------------
template<class LD, int TN, bool OBF>
__global__ void __launch_bounds__(256)
hgemm(LD ld, const __nv_bfloat16* __restrict__ Bw, int K, Epi ep) {
    constexpr int WN   = TN / 2;
    constexpr int NT8  = WN / 8;
    constexpr int NT16 = NT8 / 2;
    constexpr int NBC  = TN * 128 / (256 * 16);   // B cpa16 per thread
    constexpr uint32_t ABUF = 128 * 128;           // 16 KB
    constexpr uint32_t BBUF = (uint32_t)TN * 128;
    constexpr uint32_t STG  = ABUF + BBUF;
    extern __shared__ char dynsm[];
    const uint32_t s0 = smem_u32(dynsm);

    const int tid = threadIdx.x;
    const int wid = tid >> 5, lane = tid & 31;
    const int m0 = blockIdx.y * 128;
    const int wm = (wid >> 1) * 32;
    const int wn = (wid & 1) * WN;

    const int row = tid >> 1, half = tid & 1;
    ld.init(m0 + row);

    float acc[2][NT8][4];
#pragma unroll
    for (int i = 0; i < 2; ++i)
#pragma unroll
        for (int j = 0; j < NT8; ++j)
#pragma unroll
            for (int c = 0; c < 4; ++c) acc[i][j][c] = 0.f;

    auto fill = [&](int k0, int st) {
        bool ok;
        const __nv_bfloat16* p = ld.addr(k0 + half * 32, ok);
        uint32_t aDst = s0 + st * STG;
#pragma unroll
        for (int j = 0; j < 4; ++j) {
            uint32_t off = (uint32_t)row * 128 + half * 64 + j * 16;
            cpa16(aDst + swz(off), p + j * 8, ok);
        }
        uint32_t bDst = s0 + st * STG + ABUF;
#pragma unroll
        for (int c = 0; c < NBC; ++c) {
            int i = c * 256 + tid;
            int r = i >> 3, sg = i & 7;
            cpa16(bDst + swz((uint32_t)r * 128 + sg * 16),
                  Bw + (long)r * K + k0 + sg * 8, true);
        }
    };

    fill(0, 0);  cpa_commit();
    fill(64, 1); cpa_commit();

    int st = 0;
    for (int k0 = 0; k0 < K; k0 += 64) {
        cpa_wait<1>();
        __syncthreads();
        if (k0 + 128 < K) {
            int nst = st + 2; if (nst >= 3) nst -= 3;
            fill(k0 + 128, nst);
        }
        cpa_commit();

        const uint32_t aBase = s0 + st * STG;
        const uint32_t bBase = aBase + ABUF;
#pragma unroll
        for (int ks = 0; ks < 4; ++ks) {
            const uint32_t kb = ks * 32 + (lane >> 4) * 16;
            uint32_t af[2][4];
#pragma unroll
            for (int mi = 0; mi < 2; ++mi) {
                uint32_t r = wm + mi * 16 + (lane & 15);
                uint32_t ad = aBase + swz(r * 128 + kb);
                asm volatile("ldmatrix.sync.aligned.m8n8.x4.shared.b16 {%0,%1,%2,%3}, [%4];"
                    : "=r"(af[mi][0]), "=r"(af[mi][1]), "=r"(af[mi][2]), "=r"(af[mi][3])
                    : "r"(ad));
            }
            uint32_t bf[NT16][4];
#pragma unroll
            for (int ni = 0; ni < NT16; ++ni) {
                uint32_t r = wn + ni * 16 + (lane & 15);
                uint32_t ad = bBase + swz(r * 128 + kb);
                asm volatile("ldmatrix.sync.aligned.m8n8.x4.shared.b16 {%0,%1,%2,%3}, [%4];"
                    : "=r"(bf[ni][0]), "=r"(bf[ni][1]), "=r"(bf[ni][2]), "=r"(bf[ni][3])
                    : "r"(ad));
            }
#pragma unroll
            for (int mi = 0; mi < 2; ++mi)
#pragma unroll
                for (int ni = 0; ni < NT16; ++ni) {
                    asm volatile(
                        "mma.sync.aligned.m16n8k16.row.col.f32.bf16.bf16.f32 "
                        "{%0,%1,%2,%3}, {%4,%5,%6,%7}, {%8,%9}, {%0,%1,%2,%3};"
                        : "+f"(acc[mi][2*ni][0]), "+f"(acc[mi][2*ni][1]),
                          "+f"(acc[mi][2*ni][2]), "+f"(acc[mi][2*ni][3])
                        : "r"(af[mi][0]), "r"(af[mi][1]), "r"(af[mi][2]), "r"(af[mi][3]),
                          "r"(bf[ni][0]), "r"(bf[ni][2]));
                    asm volatile(
                        "mma.sync.aligned.m16n8k16.row.col.f32.bf16.bf16.f32 "
                        "{%0,%1,%2,%3}, {%4,%5,%6,%7}, {%8,%9}, {%0,%1,%2,%3};"
                        : "+f"(acc[mi][2*ni+1][0]), "+f"(acc[mi][2*ni+1][1]),
                          "+f"(acc[mi][2*ni+1][2]), "+f"(acc[mi][2*ni+1][3])
                        : "r"(af[mi][0]), "r"(af[mi][1]), "r"(af[mi][2]), "r"(af[mi][3]),
                          "r"(bf[ni][1]), "r"(bf[ni][3]));
                }
        }
        st = (st == 2) ? 0 : st + 1;
    }

    const int col = wn + (lane & 3) * 2;
#pragma unroll
    for (int mi = 0; mi < 2; ++mi) {
        int m1 = m0 + wm + mi * 16 + (lane >> 2);
        long b1 = epi_base(ep, m1);
        long b2 = epi_base(ep, m1 + 8);
#pragma unroll
        for (int j = 0; j < NT8; ++j) {
            int n = col + j * 8;
            float bi0 = ep.bias[n], bi1 = ep.bias[n + 1];
            float v0 = acc[mi][j][0] + bi0, v1 = acc[mi][j][1] + bi1;
            float v2 = acc[mi][j][2] + bi0, v3 = acc[mi][j][3] + bi1;
            if (ep.act) {
                v0 = fmaxf(v0, 0.f); v1 = fmaxf(v1, 0.f);
                v2 = fmaxf(v2, 0.f); v3 = fmaxf(v3, 0.f);
            }
            if (OBF) {
                __nv_bfloat16* ob = (__nv_bfloat16*)ep.out;
                __nv_bfloat162 p0 = __floats2bfloat162_rn(v0, v1);
                __nv_bfloat162 p1 = __floats2bfloat162_rn(v2, v3);
                *(uint32_t*)(ob + b1 + n) = *(uint32_t*)&p0;
                *(uint32_t*)(ob + b2 + n) = *(uint32_t*)&p1;
            } else {
                *(float2*)(ep.out + b1 + n) = make_float2(v0, v1);
                *(float2*)(ep.out + b2 + n) = make_float2(v2, v3);
            }
        }
    }
}

// ---------------- fused VQ: distances + argmin + gather(bf16) + loss ----------------
__global__ void __launch_bounds__(256)
vq_fused(const float* __restrict__ z, const float* __restrict__ emb,
         const float* __restrict__ enorm, __nv_bfloat16* __restrict__ qb) {
    __shared__ float4 se[16][16];
    __shared__ float sen[16];
    __shared__ float red[256];
    const int t = threadIdx.x;
    const long m = (long)blockIdx.x * 256 + t;
    float4 zr[16];
    const float4* zp = (const float4*)(z + m * 64);
#pragma unroll
    for (int i = 0; i < 16; ++i) zr[i] = zp[i];

    float best = 3.4e38f; int bidx = 0;
    const int ljj = t >> 4, ldd = t & 15;
    for (int j0 = 0; j0 < 512; j0 += 16) {
        __syncthreads();
        se[ljj][ldd] = ((const float4*)(emb + (long)(j0 + ljj) * 64))[ldd];
        if (t < 16) sen[t] = enorm[j0 + t];
        __syncthreads();
#pragma unroll
        for (int jj = 0; jj < 16; ++jj) {
            float s0 = 0.f, s1 = 0.f, s2 = 0.f, s3 = 0.f;
#pragma unroll
            for (int d = 0; d < 16; d += 4) {
                float4 e0 = se[jj][d+0], e1 = se[jj][d+1];
                float4 e2 = se[jj][d+2], e3 = se[jj][d+3];
                s0 = fmaf(zr[d+0].x, e0.x, s0); s0 = fmaf(zr[d+0].y, e0.y, s0);
                s0 = fmaf(zr[d+0].z, e0.z, s0); s0 = fmaf(zr[d+0].w, e0.w, s0);
                s1 = fmaf(zr[d+1].x, e1.x, s1); s1 = fmaf(zr[d+1].y, e1.y, s1);
                s1 = fmaf(zr[d+1].z, e1.z, s1); s1 = fmaf(zr[d+1].w, e1.w, s1);
                s2 = fmaf(zr[d+2].x, e2.x, s2); s2 = fmaf(zr[d+2].y, e2.y, s2);
                s2 = fmaf(zr[d+2].z, e2.z, s2); s2 = fmaf(zr[d+2].w, e2.w, s2);
                s3 = fmaf(zr[d+3].x, e3.x, s3); s3 = fmaf(zr[d+3].y, e3.y, s3);
                s3 = fmaf(zr[d+3].z, e3.z, s3); s3 = fmaf(zr[d+3].w, e3.w, s3);
            }
            float dist = sen[jj] - 2.f * ((s0 + s1) + (s2 + s3));
            if (dist < best) { best = dist; bidx = j0 + jj; }
        }
    }

    const float4* ep = (const float4*)(emb + (long)bidx * 64);
    uint2* qp = (uint2*)(qb + m * 64);
    float sq = 0.f;
#pragma unroll
    for (int i = 0; i < 16; ++i) {
        float4 e = ep[i];
        __nv_bfloat162 p0 = __floats2bfloat162_rn(e.x, e.y);
        __nv_bfloat162 p1 = __floats2bfloat162_rn(e.z, e.w);
        uint2 u; u.x = *(uint32_t*)&p0; u.y = *(uint32_t*)&p1;
        qp[i] = u;
        float d0 = e.x - zr[i].x, d1 = e.y - zr[i].y;
        float d2 = e.z - zr[i].z, d3 = e.w - zr[i].w;
        sq = fmaf(d0, d0, sq); sq = fmaf(d1, d1, sq);
        sq = fmaf(d2, d2, sq); sq = fmaf(d3, d3, sq);
    }
    red[t] = sq;
    __syncthreads();
    for (int s = 128; s; s >>= 1) {
        if (t < s) red[t] += red[t + s];
        __syncthreads();
    }
    if (t == 0) atomicAdd(&g_loss, (double)red[0]);
}

// ---------------- final deconv 64->3 k3 s1 p1 + sigmoid (bf16 in, NCHW fp32 out) ----------------
__global__ void __launch_bounds__(256)
deconv3_sigmoid(const __nv_bfloat16* __restrict__ in, const float* __restrict__ w,
                const float* __restrict__ bias, float* __restrict__ out) {
    __shared__ float sIn[8][18][66];
    __shared__ float sW[1728];
    const int t = threadIdx.x, n = blockIdx.z;
    const int y0 = blockIdx.y * 16, x0 = blockIdx.x * 64;
    for (int i = t; i < 1728; i += 256) sW[i] = w[i];
    const int ty = t >> 4, txq = t & 15;
    float acc[3][4] = {};
    for (int cc = 0; cc < 8; ++cc) {
        __syncthreads();
        for (int pos = t; pos < 18 * 66; pos += 256) {
            int sx = pos % 66, sy = pos / 66;
            int gy = y0 - 1 + sy, gx = x0 - 1 + sx;
            if (gy >= 0 && gy < 256 && gx >= 0 && gx < 256) {
                uint4 u = *(const uint4*)(in + (((long)n * 256 + gy) * 256 + gx) * 64 + cc * 8);
                float2 f0 = __bfloat1622float2(*(__nv_bfloat162*)&u.x);
                float2 f1 = __bfloat1622float2(*(__nv_bfloat162*)&u.y);
                float2 f2 = __bfloat1622float2(*(__nv_bfloat162*)&u.z);
                float2 f3 = __bfloat1622float2(*(__nv_bfloat162*)&u.w);
                sIn[0][sy][sx] = f0.x; sIn[1][sy][sx] = f0.y;
                sIn[2][sy][sx] = f1.x; sIn[3][sy][sx] = f1.y;
                sIn[4][sy][sx] = f2.x; sIn[5][sy][sx] = f2.y;
                sIn[6][sy][sx] = f3.x; sIn[7][sy][sx] = f3.y;
            } else {
#pragma unroll
                for (int c = 0; c < 8; ++c) sIn[c][sy][sx] = 0.f;
            }
        }
        __syncthreads();
#pragma unroll
        for (int c8 = 0; c8 < 8; ++c8) {
            const int ci = cc * 8 + c8;
#pragma unroll
            for (int ky = 0; ky < 3; ++ky)
#pragma unroll
            for (int kx = 0; kx < 3; ++kx) {
                const float* wp = &sW[ci*27 + ky*3 + kx];
                float w0 = wp[0], w1 = wp[9], w2 = wp[18];
                const float* ip = &sIn[c8][ty + 2 - ky][txq*4 + 2 - kx];
#pragma unroll
                for (int qq = 0; qq < 4; ++qq) {
                    float iv = ip[qq];
                    acc[0][qq] = fmaf(iv, w0, acc[0][qq]);
                    acc[1][qq] = fmaf(iv, w1, acc[1][qq]);
                    acc[2][qq] = fmaf(iv, w2, acc[2][qq]);
                }
            }
        }
    }
#pragma unroll
    for (int co = 0; co < 3; ++co) {
        float bb = bias[co];
#pragma unroll
        for (int qq = 0; qq < 4; ++qq) {
            float v = acc[co][qq] + bb;
            v = 1.f / (1.f + __expf(-v));
            out[(((long)n * 3 + co) * 256 + (y0 + ty)) * 256 + (x0 + txq*4 + qq)] = v;
        }
    }
}

// ---------------- host ----------------
static float* symaddr(const void* sym) {
    void* p = nullptr;
    cudaGetSymbolAddress(&p, sym);
    return (float*)p;
}

static Epi mk_row(float* out, const float* bias, int ldc, int act) {
    Epi e; e.out = out; e.bias = bias; e.mode = 0; e.act = act; e.ldc = ldc;
    e.MPN = e.OV = e.W2 = e.C = e.py = e.px = 0; e.nstride = 0; return e;
}
static Epi mk_dec(float* out, const float* bias, int MPN, int OV, int W2, int C,
                  int py, int px, long nstride, int act) {
    Epi e; e.out = out; e.bias = bias; e.mode = 1; e.act = act; e.ldc = 0;
    e.MPN = MPN; e.OV = OV; e.W2 = W2; e.C = C; e.py = py; e.px = px;
    e.nstride = nstride; return e;
}

typedef ConvLoaderB<64,4,4,2,1,128,128,64>   LdL2;
typedef ConvLoaderB<128,3,3,1,1,64,64,64>    LdL3;
typedef DeconvLoaderB<64,64,64>              LdD1;
typedef DeconvLoaderB<128,128,128>           LdD2;

extern "C" void kernel_launch(void* const* d_in, const int* in_sizes, int n_in,
                              void* d_out, int out_size) {
    const float* x   = (const float*)d_in[0];
    const float* w1  = (const float*)d_in[1];
    const float* b1  = (const float*)d_in[2];
    const float* w2  = (const float*)d_in[3];
    const float* b2  = (const float*)d_in[4];
    const float* w3  = (const float*)d_in[5];
    const float* b3  = (const float*)d_in[6];
    const float* emb = (const float*)d_in[7];
    const float* dw1 = (const float*)d_in[8];
    const float* db1 = (const float*)d_in[9];
    const float* dw2 = (const float*)d_in[10];
    const float* db2 = (const float*)d_in[11];
    const float* dw3 = (const float*)d_in[12];
    const float* db3 = (const float*)d_in[13];
    float* out = (float*)d_out;

    float* z   = symaddr(g_z);
    float* col = symaddr(g_col);
    float* wb1 = symaddr(g_wb1);
    float* en  = symaddr(g_enorm);
    __nv_bfloat16* h1b = (__nv_bfloat16*)symaddr(g_h1b);
    __nv_bfloat16* h2b = (__nv_bfloat16*)symaddr(g_h2b);
    __nv_bfloat16* qb  = (__nv_bfloat16*)symaddr(g_qb);
    __nv_bfloat16* d1b = (__nv_bfloat16*)symaddr(g_d1b);
    __nv_bfloat16* d2b = (__nv_bfloat16*)symaddr(g_d2b);
    __nv_bfloat16* wb2b = (__nv_bfloat16*)symaddr(g_wb2b);
    __nv_bfloat16* wb3b = (__nv_bfloat16*)symaddr(g_wb3b);
    __nv_bfloat16* wbd1 = (__nv_bfloat16*)symaddr(g_wbd1);
    __nv_bfloat16* wbd2 = (__nv_bfloat16*)symaddr(g_wbd2);

    const int SM128 = 3 * (128*128 + 128*128);   // 98304
    const int SM64  = 3 * (128*128 + 64*128);    // 73728

    static int attr_done = 0;
    if (!attr_done) {
        cudaFuncSetAttribute((const void*)hgemm<LdL2,128,true>, cudaFuncAttributeMaxDynamicSharedMemorySize, SM128);
        cudaFuncSetAttribute((const void*)hgemm<LdL3,64,false>, cudaFuncAttributeMaxDynamicSharedMemorySize, SM64);
        cudaFuncSetAttribute((const void*)hgemm<LdD1,128,true>, cudaFuncAttributeMaxDynamicSharedMemorySize, SM128);
        cudaFuncSetAttribute((const void*)hgemm<LdD2,64,true>,  cudaFuncAttributeMaxDynamicSharedMemorySize, SM64);
        attr_done = 1;
    }

    // #1: all weight packs + enorm + loss zero
    pack_all<<<1839, 256>>>(w1, w2, w3, dw1, dw2, emb);
    // #2: L1 im2col (NCHW direct)
    im2col_l1<<<32768, 256>>>(x, col);
    // #3: L1 fp32 GEMM, bf16 out
    { DenseLoader ld; ld.A = col; ld.ldk = 48;
      sgemm_t<<<dim3(1, 4096), 256>>>(ld, wb1, 48, mk_row(nullptr, b1, 64, 1), h1b); }
    // #4: L2 hgemm (ncu-profiled slot)
    { LdL2 ld; ld.in = h1b;
      hgemm<LdL2,128,true><<<dim3(1, 1024), 256, SM128>>>(ld, wb2b, 1024,
          mk_row((float*)h2b, b2, 128, 1)); }
    // #5: L3 hgemm, fp32 z out
    { LdL3 ld; ld.in = h2b;
      hgemm<LdL3,64,false><<<dim3(1, 1024), 256, SM64>>>(ld, wb3b, 1152,
          mk_row(z, b3, 64, 1)); }
    // #6: VQ
    vq_fused<<<512, 256>>>(z, emb, en, qb);

    // D1: deconv 64->128, 4 parities
    for (int p = 0; p < 4; ++p) {
        LdD1 ld; ld.in = qb; ld.py = p >> 1; ld.px = p & 1;
        hgemm<LdD1,128,true><<<dim3(1, 1024), 256, SM128>>>(ld, wbd1 + p * 32768, 256,
            mk_dec((float*)d1b, db1, 64*64, 64, 128, 128, p >> 1, p & 1, (long)128*128*128, 1));
    }
    // D2: deconv 128->64, 4 parities
    for (int p = 0; p < 4; ++p) {
        LdD2 ld; ld.in = d1b; ld.py = p >> 1; ld.px = p & 1;
        hgemm<LdD2,64,true><<<dim3(1, 4096), 256, SM64>>>(ld, wbd2 + p * 32768, 512,
            mk_dec((float*)d2b, db2, 128*128, 128, 256, 64, p >> 1, p & 1, (long)256*256*64, 1));
    }

    // D3 + sigmoid -> NCHW out
    deconv3_sigmoid<<<dim3(4, 16, 32), 256>>>(d2b, dw3, db3, out);

    finalize_loss<<<1, 1>>>(out, (long)out_size - 1);
}